// round 5
// baseline (speedup 1.0000x reference)
#include <cuda_runtime.h>
#include <math_constants.h>

#define B_      8
#define H_      8
#define T_      8192
#define DH      64
#define BUCKETS 128
#define BSZ     64
#define BH      64
#define HH      4

// scratch (device globals; no allocation allowed)
__device__ float g_bucket_sum[BH * BUCKETS * DH];   // 2 MB
__device__ float g_feat[BH * BUCKETS * 2 * DH];     // 4 MB
__device__ int   g_ridx[BH * BUCKETS];
__device__ float g_rw[BH * BUCKETS];

typedef unsigned long long u64;

__device__ __forceinline__ void fma2(u64 &d, u64 a, u64 b) {
    asm("fma.rn.f32x2 %0, %1, %2, %0;" : "+l"(d) : "l"(a), "l"(b));
}
__device__ __forceinline__ float f2sum(u64 v) {
    return __uint_as_float((unsigned)v) + __uint_as_float((unsigned)(v >> 32));
}

// ---------------------------------------------------------------------------
// Kernel 1: per-bucket sums of rotated K + first-token capture
__global__ void k_bucket_sums(const float* __restrict__ k) {
    int u = blockIdx.x, f = blockIdx.y;
    int h = f & 7; bool rot = (h >= HH);
    const float* kg = k + (size_t)f * T_ * DH;
    __shared__ float4 red[16][17];
    int cgrp = threadIdx.x & 15;
    int c4 = cgrp * 4;
    int rp = threadIdx.x >> 4;

    float4 s = {0.f, 0.f, 0.f, 0.f};
    #pragma unroll
    for (int st = 0; st < 4; st++) {
        int i = rp + 16 * st;
        int tt = u * BSZ + i;
        int src = rot ? ((tt + 63) & (T_ - 1)) : tt;
        float4 vv = *(const float4*)(kg + src * DH + c4);
        s.x += vv.x; s.y += vv.y; s.z += vv.z; s.w += vv.w;
        if (rp == 0 && st == 0)
            *(float4*)&g_feat[(f * BUCKETS + u) * 128 + 64 + c4] = vv;
    }
    red[rp][cgrp] = s;
    __syncthreads();
    if (rp == 0) {
        float4 acc = red[0][cgrp];
        #pragma unroll
        for (int r = 1; r < 16; r++) {
            float4 t2 = red[r][cgrp];
            acc.x += t2.x; acc.y += t2.y; acc.z += t2.z; acc.w += t2.w;
        }
        *(float4*)&g_bucket_sum[(f * BUCKETS + u) * DH + c4] = acc;
    }
}

// ---------------------------------------------------------------------------
// Kernel 2: smem Hillis–Steele scan over buckets -> cumavg feature
__global__ void k_prefix() {
    __shared__ float s[BUCKETS * DH];   // 32 KB
    int f = blockIdx.x, tid = threadIdx.x;
    const float* src = g_bucket_sum + (size_t)f * BUCKETS * DH;

    for (int i = tid; i < BUCKETS * DH / 4; i += 256)
        ((float4*)s)[i] = ((const float4*)src)[i];
    __syncthreads();

    #pragma unroll
    for (int off = 1; off < BUCKETS; off <<= 1) {
        float vals[32];
        #pragma unroll
        for (int t = 0; t < 32; t++) {
            int e = tid + 256 * t;
            int u = e >> 6;
            vals[t] = (u >= off) ? s[e - off * DH] : 0.f;
        }
        __syncthreads();
        #pragma unroll
        for (int t = 0; t < 32; t++) s[tid + 256 * t] += vals[t];
        __syncthreads();
    }

    for (int e = tid; e < BUCKETS * DH; e += 256) {
        int u = e >> 6, d = e & 63;
        float excl = s[e] - src[e];
        float first = g_feat[(f * BUCKETS + u) * 128 + 64 + d];
        g_feat[(f * BUCKETS + u) * 128 + d] = (excl + first) / (float)(u * BSZ + 1);
    }
}

// ---------------------------------------------------------------------------
// Kernel 3: routing
__global__ void k_route(const float* __restrict__ W) {
    int u = blockIdx.x, f = blockIdx.y, tid = threadIdx.x;
    int h = f & 7;
    __shared__ float xs[128];
    __shared__ float ls[132];
    if (tid < 128) xs[tid] = g_feat[(f * BUCKETS + u) * 128 + tid];
    __syncthreads();
    if (tid <= u) {
        float acc = 0.f;
        const float* wp = W + h * 128 * 129 + tid;
        #pragma unroll 8
        for (int d = 0; d < 128; d++) acc += xs[d] * wp[d * 129];
        ls[tid] = acc > 0.f ? acc : 0.01f * acc;
    }
    __syncthreads();
    if (tid < 32) {
        float m = -CUDART_INF_F;
        for (int c = tid; c <= u; c += 32) m = fmaxf(m, ls[c]);
        #pragma unroll
        for (int o = 16; o; o >>= 1) m = fmaxf(m, __shfl_xor_sync(~0u, m, o));
        float sum = 0.f, best = -CUDART_INF_F; int bi = 0x7fffffff;
        for (int c = tid; c <= u; c += 32) {
            float e = __expf(ls[c] - m);
            sum += e;
            if (c < u && ls[c] > best) { best = ls[c]; bi = c; }
        }
        #pragma unroll
        for (int o = 16; o; o >>= 1) {
            sum += __shfl_xor_sync(~0u, sum, o);
            float ob = __shfl_xor_sync(~0u, best, o);
            int   oi = __shfl_xor_sync(~0u, bi, o);
            if (ob > best || (ob == best && oi < bi)) { best = ob; bi = oi; }
        }
        if (tid == 0) {
            if (u == 0) { g_ridx[f * BUCKETS] = 0; g_rw[f * BUCKETS] = 0.f; }
            else {
                g_ridx[f * BUCKETS + u] = bi;
                g_rw[f * BUCKETS + u]   = __expf(best - m) / sum;
            }
        }
    }
}

// ---------------------------------------------------------------------------
// Kernel 4: fused attention tile — R2 load/softmax structure + float4 GEMMs
// QS_STRIDE=68 (17 16B-units, odd -> conflict-free LDS.128)
// PS_STRIDE=132 (33 16B-units, odd -> conflict-free LDS.128)
#define QS_STRIDE  68
#define PS_STRIDE  132
__global__ void __launch_bounds__(256, 2) k_attn(
    const float* __restrict__ q, const float* __restrict__ k, const float* __restrict__ v,
    const float* __restrict__ nullk, const float* __restrict__ nullv,
    float* __restrict__ out)
{
    extern __shared__ float sm[];
    float* Qs  = sm;                                   // [64][68]
    float* K2s = sm + 64 * QS_STRIDE;                  // [128][68]
    float* Ps  = sm;                                   // [64][132] overlay (after sync)
    float* V2T = sm + (64 + 128) * QS_STRIDE;          // [64][132]  V2T[c][j]

    int u = blockIdx.x, f = blockIdx.y, tid = threadIdx.x;
    int h = f & 7; bool rot = (h >= HH);
    const float* qg = q + (size_t)f * T_ * DH;
    const float* kg = k + (size_t)f * T_ * DH;
    const float* vg = v + (size_t)f * T_ * DH;
    int   ridx = g_ridx[f * BUCKETS + u];
    float w    = g_rw[f * BUCKETS + u];

    // ---- load phase (R2 structure): row-wise float4 gmem, scalar V2T transpose ----
    for (int idx = tid; idx < 64 * 16; idx += 256) {
        int row = idx >> 4, c4 = (idx & 15) << 2;
        int tt  = u * BSZ + row;
        int src = rot ? ((tt + 63) & (T_ - 1)) : tt;
        *(float4*)&Qs[row * QS_STRIDE + c4] = *(const float4*)(qg + src * DH + c4);
        *(float4*)&K2s[(64 + row) * QS_STRIDE + c4] = *(const float4*)(kg + src * DH + c4);
        float4 vv = *(const float4*)(vg + src * DH + c4);
        V2T[(c4 + 0) * PS_STRIDE + 64 + row] = vv.x;
        V2T[(c4 + 1) * PS_STRIDE + 64 + row] = vv.y;
        V2T[(c4 + 2) * PS_STRIDE + 64 + row] = vv.z;
        V2T[(c4 + 3) * PS_STRIDE + 64 + row] = vv.w;
        float4 rk, rv;
        if (ridx == 0) {
            rk = *(const float4*)(nullk + h * DH + c4);
            rv = *(const float4*)(nullv + h * DH + c4);
        } else {
            int st = (ridx - 1) * BSZ + row;
            int s2 = rot ? ((st + 63) & (T_ - 1)) : st;
            rk = *(const float4*)(kg + s2 * DH + c4);
            rv = *(const float4*)(vg + s2 * DH + c4);
        }
        rk.x *= w; rk.y *= w; rk.z *= w; rk.w *= w;
        *(float4*)&K2s[row * QS_STRIDE + c4] = rk;
        V2T[(c4 + 0) * PS_STRIDE + row] = rv.x * w;
        V2T[(c4 + 1) * PS_STRIDE + row] = rv.y * w;
        V2T[(c4 + 2) * PS_STRIDE + row] = rv.z * w;
        V2T[(c4 + 3) * PS_STRIDE + row] = rv.w * w;
    }
    __syncthreads();

    // ---- S = Q @ K2^T  (float4 k-chunks) ----
    int rg = tid >> 5, cg = tid & 31;
    {
        u64 acc[8][4];
        #pragma unroll
        for (int i = 0; i < 8; i++)
            #pragma unroll
            for (int j = 0; j < 4; j++) acc[i][j] = 0ull;
        #pragma unroll 2
        for (int kk = 0; kk < 64; kk += 4) {
            float4 b4[4];
            #pragma unroll
            for (int j = 0; j < 4; j++)
                b4[j] = *(const float4*)&K2s[(cg + 32 * j) * QS_STRIDE + kk];
            #pragma unroll
            for (int i = 0; i < 8; i++) {
                float4 a4 = *(const float4*)&Qs[(rg * 8 + i) * QS_STRIDE + kk];
                u64 alo = ((const u64*)&a4)[0], ahi = ((const u64*)&a4)[1];
                #pragma unroll
                for (int j = 0; j < 4; j++) {
                    fma2(acc[i][j], alo, ((const u64*)&b4[j])[0]);
                    fma2(acc[i][j], ahi, ((const u64*)&b4[j])[1]);
                }
            }
        }
        __syncthreads();  // all Qs/K2s reads done; Ps overlays them

        const float scale = 0.044194173824159216f;  // 512^-0.5
        #pragma unroll
        for (int i = 0; i < 8; i++)
            #pragma unroll
            for (int j = 0; j < 4; j++)
                Ps[(rg * 8 + i) * PS_STRIDE + (cg + 32 * j)] = f2sum(acc[i][j]) * scale;
    }
    __syncthreads();

    // ---- masked softmax: warp per 8 rows ----
    {
        int warp = tid >> 5, lane = tid & 31;
        for (int rr = 0; rr < 8; rr++) {
            int r = warp * 8 + rr;
            bool special = rot && (u == BUCKETS - 1) && (r >= 1);
            float vals[4]; bool al[4];
            #pragma unroll
            for (int s = 0; s < 4; s++) {
                int j = lane + 32 * s;
                vals[s] = Ps[r * PS_STRIDE + j];
                bool a = (j < 64) ? true : ((j - 64) <= r);
                if (special && j <= 64) a = false;
                al[s] = a;
            }
            float m = -CUDART_INF_F;
            #pragma unroll
            for (int s = 0; s < 4; s++) if (al[s]) m = fmaxf(m, vals[s]);
            #pragma unroll
            for (int o = 16; o; o >>= 1) m = fmaxf(m, __shfl_xor_sync(~0u, m, o));
            float e[4], sum = 0.f;
            #pragma unroll
            for (int s = 0; s < 4; s++) { e[s] = al[s] ? __expf(vals[s] - m) : 0.f; sum += e[s]; }
            #pragma unroll
            for (int o = 16; o; o >>= 1) sum += __shfl_xor_sync(~0u, sum, o);
            float inv = 1.f / sum;
            #pragma unroll
            for (int s = 0; s < 4; s++) Ps[r * PS_STRIDE + lane + 32 * s] = e[s] * inv;
        }
    }
    __syncthreads();

    // ---- O = P @ V2  (float4 j-chunks) ----
    u64 o2[8][2];
    #pragma unroll
    for (int i = 0; i < 8; i++) { o2[i][0] = 0ull; o2[i][1] = 0ull; }
    #pragma unroll 2
    for (int j = 0; j < 128; j += 4) {
        float4 b40 = *(const float4*)&V2T[(cg +  0) * PS_STRIDE + j];
        float4 b41 = *(const float4*)&V2T[(cg + 32) * PS_STRIDE + j];
        u64 b0lo = ((const u64*)&b40)[0], b0hi = ((const u64*)&b40)[1];
        u64 b1lo = ((const u64*)&b41)[0], b1hi = ((const u64*)&b41)[1];
        #pragma unroll
        for (int i = 0; i < 8; i++) {
            float4 a4 = *(const float4*)&Ps[(rg * 8 + i) * PS_STRIDE + j];
            u64 alo = ((const u64*)&a4)[0], ahi = ((const u64*)&a4)[1];
            fma2(o2[i][0], alo, b0lo);
            fma2(o2[i][0], ahi, b0hi);
            fma2(o2[i][1], alo, b1lo);
            fma2(o2[i][1], ahi, b1hi);
        }
    }

    float* og = out + (size_t)f * T_ * DH;
    #pragma unroll
    for (int i = 0; i < 8; i++) {
        int r  = rg * 8 + i;
        int tt = u * BSZ + r;
        int dst = rot ? ((tt + 63) & (T_ - 1)) : tt;
        og[dst * DH + cg]      = f2sum(o2[i][0]);
        og[dst * DH + cg + 32] = f2sum(o2[i][1]);
    }
}

// ---------------------------------------------------------------------------
extern "C" void kernel_launch(void* const* d_in, const int* in_sizes, int n_in,
                              void* d_out, int out_size) {
    const float* q  = (const float*)d_in[0];
    const float* k  = (const float*)d_in[1];
    const float* v  = (const float*)d_in[2];
    const float* W  = (const float*)d_in[3];
    const float* nk = (const float*)d_in[4];
    const float* nv = (const float*)d_in[5];
    float* out = (float*)d_out;

    k_bucket_sums<<<dim3(BUCKETS, BH), 256>>>(k);
    k_prefix<<<BH, 256>>>();
    k_route<<<dim3(BUCKETS, BH), 256>>>(W);

    const size_t smem = (size_t)((64 + 128) * QS_STRIDE + 64 * PS_STRIDE) * sizeof(float); // 86016 B
    cudaFuncSetAttribute(k_attn, cudaFuncAttributeMaxDynamicSharedMemorySize, (int)smem);
    k_attn<<<dim3(BUCKETS, BH), 256, smem>>>(q, k, v, nk, nv, out);
}

// round 7
// speedup vs baseline: 1.0224x; 1.0224x over previous
#include <cuda_runtime.h>
#include <math_constants.h>

#define B_      8
#define H_      8
#define T_      8192
#define DH      64
#define BUCKETS 128
#define BSZ     64
#define BH      64
#define HH      4

// scratch (device globals; no allocation allowed)
__device__ float g_bucket_sum[BH * BUCKETS * DH];   // 2 MB
__device__ float g_feat[BH * BUCKETS * 2 * DH];     // 4 MB
__device__ int   g_ridx[BH * BUCKETS];
__device__ float g_rw[BH * BUCKETS];

typedef unsigned long long u64;

__device__ __forceinline__ void fma2(u64 &d, u64 a, u64 b) {
    asm("fma.rn.f32x2 %0, %1, %2, %0;" : "+l"(d) : "l"(a), "l"(b));
}
__device__ __forceinline__ float f2sum(u64 v) {
    return __uint_as_float((unsigned)v) + __uint_as_float((unsigned)(v >> 32));
}

// ---------------------------------------------------------------------------
// Kernel 1: per-bucket sums of rotated K + first-token capture
__global__ void k_bucket_sums(const float* __restrict__ k) {
    int u = blockIdx.x, f = blockIdx.y;
    int h = f & 7; bool rot = (h >= HH);
    const float* kg = k + (size_t)f * T_ * DH;
    __shared__ float4 red[16][17];
    int cgrp = threadIdx.x & 15;
    int c4 = cgrp * 4;
    int rp = threadIdx.x >> 4;

    float4 s = {0.f, 0.f, 0.f, 0.f};
    #pragma unroll
    for (int st = 0; st < 4; st++) {
        int i = rp + 16 * st;
        int tt = u * BSZ + i;
        int src = rot ? ((tt + 63) & (T_ - 1)) : tt;
        float4 vv = *(const float4*)(kg + src * DH + c4);
        s.x += vv.x; s.y += vv.y; s.z += vv.z; s.w += vv.w;
        if (rp == 0 && st == 0)
            *(float4*)&g_feat[(f * BUCKETS + u) * 128 + 64 + c4] = vv;
    }
    red[rp][cgrp] = s;
    __syncthreads();
    if (rp == 0) {
        float4 acc = red[0][cgrp];
        #pragma unroll
        for (int r = 1; r < 16; r++) {
            float4 t2 = red[r][cgrp];
            acc.x += t2.x; acc.y += t2.y; acc.z += t2.z; acc.w += t2.w;
        }
        *(float4*)&g_bucket_sum[(f * BUCKETS + u) * DH + c4] = acc;
    }
}

// ---------------------------------------------------------------------------
// Kernel 2: smem Hillis–Steele scan over buckets -> cumavg feature
__global__ void k_prefix() {
    __shared__ float s[BUCKETS * DH];   // 32 KB
    int f = blockIdx.x, tid = threadIdx.x;
    const float* src = g_bucket_sum + (size_t)f * BUCKETS * DH;

    for (int i = tid; i < BUCKETS * DH / 4; i += 256)
        ((float4*)s)[i] = ((const float4*)src)[i];
    __syncthreads();

    #pragma unroll
    for (int off = 1; off < BUCKETS; off <<= 1) {
        float vals[32];
        #pragma unroll
        for (int t = 0; t < 32; t++) {
            int e = tid + 256 * t;
            int u = e >> 6;
            vals[t] = (u >= off) ? s[e - off * DH] : 0.f;
        }
        __syncthreads();
        #pragma unroll
        for (int t = 0; t < 32; t++) s[tid + 256 * t] += vals[t];
        __syncthreads();
    }

    for (int e = tid; e < BUCKETS * DH; e += 256) {
        int u = e >> 6, d = e & 63;
        float excl = s[e] - src[e];
        float first = g_feat[(f * BUCKETS + u) * 128 + 64 + d];
        g_feat[(f * BUCKETS + u) * 128 + d] = (excl + first) / (float)(u * BSZ + 1);
    }
}

// ---------------------------------------------------------------------------
// Kernel 3: routing
__global__ void k_route(const float* __restrict__ W) {
    int u = blockIdx.x, f = blockIdx.y, tid = threadIdx.x;
    int h = f & 7;
    __shared__ float xs[128];
    __shared__ float ls[132];
    if (tid < 128) xs[tid] = g_feat[(f * BUCKETS + u) * 128 + tid];
    __syncthreads();
    if (tid <= u) {
        float acc = 0.f;
        const float* wp = W + h * 128 * 129 + tid;
        #pragma unroll 8
        for (int d = 0; d < 128; d++) acc += xs[d] * wp[d * 129];
        ls[tid] = acc > 0.f ? acc : 0.01f * acc;
    }
    __syncthreads();
    if (tid < 32) {
        float m = -CUDART_INF_F;
        for (int c = tid; c <= u; c += 32) m = fmaxf(m, ls[c]);
        #pragma unroll
        for (int o = 16; o; o >>= 1) m = fmaxf(m, __shfl_xor_sync(~0u, m, o));
        float sum = 0.f, best = -CUDART_INF_F; int bi = 0x7fffffff;
        for (int c = tid; c <= u; c += 32) {
            float e = __expf(ls[c] - m);
            sum += e;
            if (c < u && ls[c] > best) { best = ls[c]; bi = c; }
        }
        #pragma unroll
        for (int o = 16; o; o >>= 1) {
            sum += __shfl_xor_sync(~0u, sum, o);
            float ob = __shfl_xor_sync(~0u, best, o);
            int   oi = __shfl_xor_sync(~0u, bi, o);
            if (ob > best || (ob == best && oi < bi)) { best = ob; bi = oi; }
        }
        if (tid == 0) {
            if (u == 0) { g_ridx[f * BUCKETS] = 0; g_rw[f * BUCKETS] = 0.f; }
            else {
                g_ridx[f * BUCKETS + u] = bi;
                g_rw[f * BUCKETS + u]   = __expf(best - m) / sum;
            }
        }
    }
}

// ---------------------------------------------------------------------------
// Kernel 4: fused attention tile — hybrid operand widths
//   Qs  stride 68 (float4 broadcasts, 16B-aligned rows)
//   K2s stride 66 (u64 b-loads, odd u64 stride -> conflict-free)
//   Ps  stride 132 (float4 broadcasts)
//   V2T stride 130 (u64 b-loads, odd u64 stride -> conflict-free)
#define Q_STR   68
#define K_STR   66
#define P_STR   132
#define V_STR   130
__global__ void __launch_bounds__(256, 2) k_attn(
    const float* __restrict__ q, const float* __restrict__ k, const float* __restrict__ v,
    const float* __restrict__ nullk, const float* __restrict__ nullv,
    float* __restrict__ out)
{
    extern __shared__ float sm[];
    float* Qs  = sm;                                   // [64][68]
    float* K2s = sm + 64 * Q_STR;                      // [128][66]
    float* Ps  = sm;                                   // [64][132] overlay (after sync)
    float* V2T = sm + 64 * Q_STR + 128 * K_STR;        // [64][130]  V2T[c][j]

    int u = blockIdx.x, f = blockIdx.y, tid = threadIdx.x;
    int h = f & 7; bool rot = (h >= HH);
    const float* qg = q + (size_t)f * T_ * DH;
    const float* kg = k + (size_t)f * T_ * DH;
    const float* vg = v + (size_t)f * T_ * DH;
    int   ridx = g_ridx[f * BUCKETS + u];
    float w    = g_rw[f * BUCKETS + u];

    // ---- load phase (R2/R4 structure) ----
    for (int idx = tid; idx < 64 * 16; idx += 256) {
        int row = idx >> 4, c4 = (idx & 15) << 2;
        int tt  = u * BSZ + row;
        int src = rot ? ((tt + 63) & (T_ - 1)) : tt;
        *(float4*)&Qs[row * Q_STR + c4] = *(const float4*)(qg + src * DH + c4);
        float4 kv = *(const float4*)(kg + src * DH + c4);
        *(float2*)&K2s[(64 + row) * K_STR + c4]     = make_float2(kv.x, kv.y);
        *(float2*)&K2s[(64 + row) * K_STR + c4 + 2] = make_float2(kv.z, kv.w);
        float4 vv = *(const float4*)(vg + src * DH + c4);
        V2T[(c4 + 0) * V_STR + 64 + row] = vv.x;
        V2T[(c4 + 1) * V_STR + 64 + row] = vv.y;
        V2T[(c4 + 2) * V_STR + 64 + row] = vv.z;
        V2T[(c4 + 3) * V_STR + 64 + row] = vv.w;
        float4 rk, rv;
        if (ridx == 0) {
            rk = *(const float4*)(nullk + h * DH + c4);
            rv = *(const float4*)(nullv + h * DH + c4);
        } else {
            int st = (ridx - 1) * BSZ + row;
            int s2 = rot ? ((st + 63) & (T_ - 1)) : st;
            rk = *(const float4*)(kg + s2 * DH + c4);
            rv = *(const float4*)(vg + s2 * DH + c4);
        }
        rk.x *= w; rk.y *= w; rk.z *= w; rk.w *= w;
        *(float2*)&K2s[row * K_STR + c4]     = make_float2(rk.x, rk.y);
        *(float2*)&K2s[row * K_STR + c4 + 2] = make_float2(rk.z, rk.w);
        V2T[(c4 + 0) * V_STR + row] = rv.x * w;
        V2T[(c4 + 1) * V_STR + row] = rv.y * w;
        V2T[(c4 + 2) * V_STR + row] = rv.z * w;
        V2T[(c4 + 3) * V_STR + row] = rv.w * w;
    }
    __syncthreads();

    // ---- S = Q @ K2^T : float4 a-broadcast + u64 b ----
    int rg = tid >> 5, cg = tid & 31;
    {
        u64 acc[8][4];
        #pragma unroll
        for (int i = 0; i < 8; i++)
            #pragma unroll
            for (int j = 0; j < 4; j++) acc[i][j] = 0ull;
        #pragma unroll 2
        for (int kk = 0; kk < 64; kk += 4) {
            u64 b2[8];
            #pragma unroll
            for (int j = 0; j < 4; j++) {
                b2[2 * j]     = *(const u64*)&K2s[(cg + 32 * j) * K_STR + kk];
                b2[2 * j + 1] = *(const u64*)&K2s[(cg + 32 * j) * K_STR + kk + 2];
            }
            #pragma unroll
            for (int i = 0; i < 8; i++) {
                float4 a4 = *(const float4*)&Qs[(rg * 8 + i) * Q_STR + kk];
                u64 alo = ((const u64*)&a4)[0], ahi = ((const u64*)&a4)[1];
                #pragma unroll
                for (int j = 0; j < 4; j++) {
                    fma2(acc[i][j], alo, b2[2 * j]);
                    fma2(acc[i][j], ahi, b2[2 * j + 1]);
                }
            }
        }
        __syncthreads();  // all Qs/K2s reads done; Ps overlays them

        const float scale = 0.044194173824159216f;  // 512^-0.5
        #pragma unroll
        for (int i = 0; i < 8; i++)
            #pragma unroll
            for (int j = 0; j < 4; j++)
                Ps[(rg * 8 + i) * P_STR + (cg + 32 * j)] = f2sum(acc[i][j]) * scale;
    }
    __syncthreads();

    // ---- masked softmax: warp per 8 rows ----
    {
        int warp = tid >> 5, lane = tid & 31;
        for (int rr = 0; rr < 8; rr++) {
            int r = warp * 8 + rr;
            bool special = rot && (u == BUCKETS - 1) && (r >= 1);
            float vals[4]; bool al[4];
            #pragma unroll
            for (int s = 0; s < 4; s++) {
                int j = lane + 32 * s;
                vals[s] = Ps[r * P_STR + j];
                bool a = (j < 64) ? true : ((j - 64) <= r);
                if (special && j <= 64) a = false;
                al[s] = a;
            }
            float m = -CUDART_INF_F;
            #pragma unroll
            for (int s = 0; s < 4; s++) if (al[s]) m = fmaxf(m, vals[s]);
            #pragma unroll
            for (int o = 16; o; o >>= 1) m = fmaxf(m, __shfl_xor_sync(~0u, m, o));
            float e[4], sum = 0.f;
            #pragma unroll
            for (int s = 0; s < 4; s++) { e[s] = al[s] ? __expf(vals[s] - m) : 0.f; sum += e[s]; }
            #pragma unroll
            for (int o = 16; o; o >>= 1) sum += __shfl_xor_sync(~0u, sum, o);
            float inv = 1.f / sum;
            #pragma unroll
            for (int s = 0; s < 4; s++) Ps[r * P_STR + lane + 32 * s] = e[s] * inv;
        }
    }
    __syncthreads();

    // ---- O = P @ V2 : float4 a-broadcast + u64 b ----
    u64 o2[8][2];
    #pragma unroll
    for (int i = 0; i < 8; i++) { o2[i][0] = 0ull; o2[i][1] = 0ull; }
    #pragma unroll 2
    for (int j = 0; j < 128; j += 4) {
        u64 b2[4];
        b2[0] = *(const u64*)&V2T[(cg +  0) * V_STR + j];
        b2[1] = *(const u64*)&V2T[(cg +  0) * V_STR + j + 2];
        b2[2] = *(const u64*)&V2T[(cg + 32) * V_STR + j];
        b2[3] = *(const u64*)&V2T[(cg + 32) * V_STR + j + 2];
        #pragma unroll
        for (int i = 0; i < 8; i++) {
            float4 a4 = *(const float4*)&Ps[(rg * 8 + i) * P_STR + j];
            u64 alo = ((const u64*)&a4)[0], ahi = ((const u64*)&a4)[1];
            fma2(o2[i][0], alo, b2[0]);
            fma2(o2[i][0], ahi, b2[1]);
            fma2(o2[i][1], alo, b2[2]);
            fma2(o2[i][1], ahi, b2[3]);
        }
    }

    float* og = out + (size_t)f * T_ * DH;
    #pragma unroll
    for (int i = 0; i < 8; i++) {
        int r  = rg * 8 + i;
        int tt = u * BSZ + r;
        int dst = rot ? ((tt + 63) & (T_ - 1)) : tt;
        og[dst * DH + cg]      = f2sum(o2[i][0]);
        og[dst * DH + cg + 32] = f2sum(o2[i][1]);
    }
}

// ---------------------------------------------------------------------------
extern "C" void kernel_launch(void* const* d_in, const int* in_sizes, int n_in,
                              void* d_out, int out_size) {
    const float* q  = (const float*)d_in[0];
    const float* k  = (const float*)d_in[1];
    const float* v  = (const float*)d_in[2];
    const float* W  = (const float*)d_in[3];
    const float* nk = (const float*)d_in[4];
    const float* nv = (const float*)d_in[5];
    float* out = (float*)d_out;

    k_bucket_sums<<<dim3(BUCKETS, BH), 256>>>(k);
    k_prefix<<<BH, 256>>>();
    k_route<<<dim3(BUCKETS, BH), 256>>>(W);

    const size_t smem = (size_t)(64 * Q_STR + 128 * K_STR + 64 * V_STR) * sizeof(float); // 84480 B
    cudaFuncSetAttribute(k_attn, cudaFuncAttributeMaxDynamicSharedMemorySize, (int)smem);
    k_attn<<<dim3(BUCKETS, BH), 256, smem>>>(q, k, v, nk, nv, out);
}

// round 8
// speedup vs baseline: 1.1456x; 1.1206x over previous
#include <cuda_runtime.h>
#include <math_constants.h>

#define B_      8
#define H_      8
#define T_      8192
#define DH      64
#define BUCKETS 128
#define BSZ     64
#define BH      64
#define HH      4

// scratch (device globals; no allocation allowed)
__device__ float g_bucket_sum[BH * BUCKETS * DH];   // 2 MB
__device__ float g_feat[BH * BUCKETS * 2 * DH];     // 4 MB
__device__ int   g_ridx[BH * BUCKETS];
__device__ float g_rw[BH * BUCKETS];

typedef unsigned long long u64;

__device__ __forceinline__ void fma2(u64 &d, u64 a, u64 b) {
    asm("fma.rn.f32x2 %0, %1, %2, %0;" : "+l"(d) : "l"(a), "l"(b));
}
__device__ __forceinline__ float f2sum(u64 v) {
    return __uint_as_float((unsigned)v) + __uint_as_float((unsigned)(v >> 32));
}

// ---------------------------------------------------------------------------
// Kernel 1: per-bucket sums of rotated K + first-token capture
__global__ void k_bucket_sums(const float* __restrict__ k) {
    int u = blockIdx.x, f = blockIdx.y;
    int h = f & 7; bool rot = (h >= HH);
    const float* kg = k + (size_t)f * T_ * DH;
    __shared__ float4 red[16][17];
    int cgrp = threadIdx.x & 15;
    int c4 = cgrp * 4;
    int rp = threadIdx.x >> 4;

    float4 s = {0.f, 0.f, 0.f, 0.f};
    #pragma unroll
    for (int st = 0; st < 4; st++) {
        int i = rp + 16 * st;
        int tt = u * BSZ + i;
        int src = rot ? ((tt + 63) & (T_ - 1)) : tt;
        float4 vv = *(const float4*)(kg + src * DH + c4);
        s.x += vv.x; s.y += vv.y; s.z += vv.z; s.w += vv.w;
        if (rp == 0 && st == 0)
            *(float4*)&g_feat[(f * BUCKETS + u) * 128 + 64 + c4] = vv;
    }
    red[rp][cgrp] = s;
    __syncthreads();
    if (rp == 0) {
        float4 acc = red[0][cgrp];
        #pragma unroll
        for (int r = 1; r < 16; r++) {
            float4 t2 = red[r][cgrp];
            acc.x += t2.x; acc.y += t2.y; acc.z += t2.z; acc.w += t2.w;
        }
        *(float4*)&g_bucket_sum[(f * BUCKETS + u) * DH + c4] = acc;
    }
}

// ---------------------------------------------------------------------------
// Kernel 2: smem Hillis–Steele scan over buckets -> cumavg feature
__global__ void k_prefix() {
    __shared__ float s[BUCKETS * DH];   // 32 KB
    int f = blockIdx.x, tid = threadIdx.x;
    const float* src = g_bucket_sum + (size_t)f * BUCKETS * DH;

    for (int i = tid; i < BUCKETS * DH / 4; i += 256)
        ((float4*)s)[i] = ((const float4*)src)[i];
    __syncthreads();

    #pragma unroll
    for (int off = 1; off < BUCKETS; off <<= 1) {
        float vals[32];
        #pragma unroll
        for (int t = 0; t < 32; t++) {
            int e = tid + 256 * t;
            int u = e >> 6;
            vals[t] = (u >= off) ? s[e - off * DH] : 0.f;
        }
        __syncthreads();
        #pragma unroll
        for (int t = 0; t < 32; t++) s[tid + 256 * t] += vals[t];
        __syncthreads();
    }

    for (int e = tid; e < BUCKETS * DH; e += 256) {
        int u = e >> 6, d = e & 63;
        float excl = s[e] - src[e];
        float first = g_feat[(f * BUCKETS + u) * 128 + 64 + d];
        g_feat[(f * BUCKETS + u) * 128 + d] = (excl + first) / (float)(u * BSZ + 1);
    }
}

// ---------------------------------------------------------------------------
// Kernel 3: routing
__global__ void k_route(const float* __restrict__ W) {
    int u = blockIdx.x, f = blockIdx.y, tid = threadIdx.x;
    int h = f & 7;
    __shared__ float xs[128];
    __shared__ float ls[132];
    if (tid < 128) xs[tid] = g_feat[(f * BUCKETS + u) * 128 + tid];
    __syncthreads();
    if (tid <= u) {
        float acc = 0.f;
        const float* wp = W + h * 128 * 129 + tid;
        #pragma unroll 8
        for (int d = 0; d < 128; d++) acc += xs[d] * wp[d * 129];
        ls[tid] = acc > 0.f ? acc : 0.01f * acc;
    }
    __syncthreads();
    if (tid < 32) {
        float m = -CUDART_INF_F;
        for (int c = tid; c <= u; c += 32) m = fmaxf(m, ls[c]);
        #pragma unroll
        for (int o = 16; o; o >>= 1) m = fmaxf(m, __shfl_xor_sync(~0u, m, o));
        float sum = 0.f, best = -CUDART_INF_F; int bi = 0x7fffffff;
        for (int c = tid; c <= u; c += 32) {
            float e = __expf(ls[c] - m);
            sum += e;
            if (c < u && ls[c] > best) { best = ls[c]; bi = c; }
        }
        #pragma unroll
        for (int o = 16; o; o >>= 1) {
            sum += __shfl_xor_sync(~0u, sum, o);
            float ob = __shfl_xor_sync(~0u, best, o);
            int   oi = __shfl_xor_sync(~0u, bi, o);
            if (ob > best || (ob == best && oi < bi)) { best = ob; bi = oi; }
        }
        if (tid == 0) {
            if (u == 0) { g_ridx[f * BUCKETS] = 0; g_rw[f * BUCKETS] = 0.f; }
            else {
                g_ridx[f * BUCKETS + u] = bi;
                g_rw[f * BUCKETS + u]   = __expf(best - m) / sum;
            }
        }
    }
}

// ---------------------------------------------------------------------------
// Kernel 4: fused attention tile — R4 structure + causal work skipping
#define QS_STRIDE  66
#define PS_STRIDE  130
__global__ void __launch_bounds__(256, 2) k_attn(
    const float* __restrict__ q, const float* __restrict__ k, const float* __restrict__ v,
    const float* __restrict__ nullk, const float* __restrict__ nullv,
    float* __restrict__ out)
{
    extern __shared__ float sm[];
    float* Qs  = sm;                                   // [64][66]
    float* K2s = sm + 64 * QS_STRIDE;                  // [128][66]
    float* Ps  = sm;                                   // [64][130] overlay (after sync)
    float* V2T = sm + (64 + 128) * QS_STRIDE;          // [64][130]  V2T[c][j]

    int u = blockIdx.x, f = blockIdx.y, tid = threadIdx.x;
    int h = f & 7; bool rot = (h >= HH);
    const float* qg = q + (size_t)f * T_ * DH;
    const float* kg = k + (size_t)f * T_ * DH;
    const float* vg = v + (size_t)f * T_ * DH;
    int   ridx = g_ridx[f * BUCKETS + u];
    float w    = g_rw[f * BUCKETS + u];

    // ---- load Q, K2 (routed|own), V2T (routed|own transposed) ----
    for (int idx = tid; idx < 64 * 16; idx += 256) {
        int row = idx >> 4, c4 = (idx & 15) << 2;
        int tt  = u * BSZ + row;
        int src = rot ? ((tt + 63) & (T_ - 1)) : tt;
        float4 qv = *(const float4*)(qg + src * DH + c4);
        *(float2*)&Qs[row * QS_STRIDE + c4]     = make_float2(qv.x, qv.y);
        *(float2*)&Qs[row * QS_STRIDE + c4 + 2] = make_float2(qv.z, qv.w);
        float4 kv = *(const float4*)(kg + src * DH + c4);
        *(float2*)&K2s[(64 + row) * QS_STRIDE + c4]     = make_float2(kv.x, kv.y);
        *(float2*)&K2s[(64 + row) * QS_STRIDE + c4 + 2] = make_float2(kv.z, kv.w);
        float4 vv = *(const float4*)(vg + src * DH + c4);
        V2T[(c4 + 0) * PS_STRIDE + 64 + row] = vv.x;
        V2T[(c4 + 1) * PS_STRIDE + 64 + row] = vv.y;
        V2T[(c4 + 2) * PS_STRIDE + 64 + row] = vv.z;
        V2T[(c4 + 3) * PS_STRIDE + 64 + row] = vv.w;
        float4 rk, rv;
        if (ridx == 0) {
            rk = *(const float4*)(nullk + h * DH + c4);
            rv = *(const float4*)(nullv + h * DH + c4);
        } else {
            int st = (ridx - 1) * BSZ + row;
            int s2 = rot ? ((st + 63) & (T_ - 1)) : st;
            rk = *(const float4*)(kg + s2 * DH + c4);
            rv = *(const float4*)(vg + s2 * DH + c4);
        }
        rk.x *= w; rk.y *= w; rk.z *= w; rk.w *= w;
        *(float2*)&K2s[row * QS_STRIDE + c4]     = make_float2(rk.x, rk.y);
        *(float2*)&K2s[row * QS_STRIDE + c4 + 2] = make_float2(rk.z, rk.w);
        V2T[(c4 + 0) * PS_STRIDE + row] = rv.x * w;
        V2T[(c4 + 1) * PS_STRIDE + row] = rv.y * w;
        V2T[(c4 + 2) * PS_STRIDE + row] = rv.z * w;
        V2T[(c4 + 3) * PS_STRIDE + row] = rv.w * w;
    }
    __syncthreads();

    // ---- S = Q @ K2^T with causal col-group skip ----
    // warps 0-3 (rows 0-31): cols 96-127 (own-offset 32-63 > r) are fully masked
    // -> compute only 3 col-groups. Softmax later writes zeros there.
    int rg = tid >> 5, cg = tid & 31;
    u64 acc[8][4];
    #pragma unroll
    for (int i = 0; i < 8; i++)
        #pragma unroll
        for (int j = 0; j < 4; j++) acc[i][j] = 0ull;

    if (rg >= 4) {
        #pragma unroll 2
        for (int kk = 0; kk < 64; kk += 2) {
            u64 a2[8], b2[4];
            #pragma unroll
            for (int i = 0; i < 8; i++) a2[i] = *(const u64*)&Qs[(rg * 8 + i) * QS_STRIDE + kk];
            #pragma unroll
            for (int j = 0; j < 4; j++) b2[j] = *(const u64*)&K2s[(cg + 32 * j) * QS_STRIDE + kk];
            #pragma unroll
            for (int i = 0; i < 8; i++)
                #pragma unroll
                for (int j = 0; j < 4; j++) fma2(acc[i][j], a2[i], b2[j]);
        }
    } else {
        #pragma unroll 2
        for (int kk = 0; kk < 64; kk += 2) {
            u64 a2[8], b2[3];
            #pragma unroll
            for (int i = 0; i < 8; i++) a2[i] = *(const u64*)&Qs[(rg * 8 + i) * QS_STRIDE + kk];
            #pragma unroll
            for (int j = 0; j < 3; j++) b2[j] = *(const u64*)&K2s[(cg + 32 * j) * QS_STRIDE + kk];
            #pragma unroll
            for (int i = 0; i < 8; i++)
                #pragma unroll
                for (int j = 0; j < 3; j++) fma2(acc[i][j], a2[i], b2[j]);
        }
    }
    __syncthreads();  // all Qs/K2s reads done; Ps overlays them

    {
        const float scale = 0.044194173824159216f;  // 512^-0.5
        #pragma unroll
        for (int i = 0; i < 8; i++)
            #pragma unroll
            for (int j = 0; j < 3; j++)
                Ps[(rg * 8 + i) * PS_STRIDE + (cg + 32 * j)] = f2sum(acc[i][j]) * scale;
        if (rg >= 4) {
            #pragma unroll
            for (int i = 0; i < 8; i++)
                Ps[(rg * 8 + i) * PS_STRIDE + (cg + 96)] = f2sum(acc[i][3]) * scale;
        }
    }
    __syncthreads();

    // ---- masked softmax: warp per 8 rows (writes zeros in masked cols,
    //      including the uncomputed group-3 for rows < 32) ----
    {
        int warp = tid >> 5, lane = tid & 31;
        for (int rr = 0; rr < 8; rr++) {
            int r = warp * 8 + rr;
            bool special = rot && (u == BUCKETS - 1) && (r >= 1);
            float vals[4]; bool al[4];
            #pragma unroll
            for (int s = 0; s < 4; s++) {
                int j = lane + 32 * s;
                vals[s] = Ps[r * PS_STRIDE + j];
                bool a = (j < 64) ? true : ((j - 64) <= r);
                if (special && j <= 64) a = false;
                al[s] = a;
            }
            float m = -CUDART_INF_F;
            #pragma unroll
            for (int s = 0; s < 4; s++) if (al[s]) m = fmaxf(m, vals[s]);
            #pragma unroll
            for (int o = 16; o; o >>= 1) m = fmaxf(m, __shfl_xor_sync(~0u, m, o));
            float e[4], sum = 0.f;
            #pragma unroll
            for (int s = 0; s < 4; s++) { e[s] = al[s] ? __expf(vals[s] - m) : 0.f; sum += e[s]; }
            #pragma unroll
            for (int o = 16; o; o >>= 1) sum += __shfl_xor_sync(~0u, sum, o);
            float inv = 1.f / sum;
            #pragma unroll
            for (int s = 0; s < 4; s++) Ps[r * PS_STRIDE + lane + 32 * s] = e[s] * inv;
        }
    }
    __syncthreads();

    // ---- O = P @ V2 with per-warp causal j-bound ----
    // rows rg*8..rg*8+7 need j < 72 + 8*rg (P is zero beyond; skip the work)
    u64 o2[8][2];
    #pragma unroll
    for (int i = 0; i < 8; i++) { o2[i][0] = 0ull; o2[i][1] = 0ull; }
    int jmax = 72 + 8 * rg;   // 72,80,...,128
    #pragma unroll 4
    for (int j = 0; j < jmax; j += 2) {
        u64 a2[8], b2[2];
        #pragma unroll
        for (int i = 0; i < 8; i++) a2[i] = *(const u64*)&Ps[(rg * 8 + i) * PS_STRIDE + j];
        b2[0] = *(const u64*)&V2T[(cg +  0) * PS_STRIDE + j];
        b2[1] = *(const u64*)&V2T[(cg + 32) * PS_STRIDE + j];
        #pragma unroll
        for (int i = 0; i < 8; i++) {
            fma2(o2[i][0], a2[i], b2[0]);
            fma2(o2[i][1], a2[i], b2[1]);
        }
    }

    float* og = out + (size_t)f * T_ * DH;
    #pragma unroll
    for (int i = 0; i < 8; i++) {
        int r  = rg * 8 + i;
        int tt = u * BSZ + r;
        int dst = rot ? ((tt + 63) & (T_ - 1)) : tt;
        og[dst * DH + cg]      = f2sum(o2[i][0]);
        og[dst * DH + cg + 32] = f2sum(o2[i][1]);
    }
}

// ---------------------------------------------------------------------------
extern "C" void kernel_launch(void* const* d_in, const int* in_sizes, int n_in,
                              void* d_out, int out_size) {
    const float* q  = (const float*)d_in[0];
    const float* k  = (const float*)d_in[1];
    const float* v  = (const float*)d_in[2];
    const float* W  = (const float*)d_in[3];
    const float* nk = (const float*)d_in[4];
    const float* nv = (const float*)d_in[5];
    float* out = (float*)d_out;

    k_bucket_sums<<<dim3(BUCKETS, BH), 256>>>(k);
    k_prefix<<<BH, 256>>>();
    k_route<<<dim3(BUCKETS, BH), 256>>>(W);

    const size_t smem = (size_t)((64 + 128) * QS_STRIDE + 64 * PS_STRIDE) * sizeof(float); // 83968 B
    cudaFuncSetAttribute(k_attn, cudaFuncAttributeMaxDynamicSharedMemorySize, (int)smem);
    k_attn<<<dim3(BUCKETS, BH), 256, smem>>>(q, k, v, nk, nv, out);
}